// round 5
// baseline (speedup 1.0000x reference)
#include <cuda_runtime.h>
#include <cuda_bf16.h>
#include <cstdint>

// ---------------------------------------------------------------------------
// MultiWorldSSM: emb-gather -> router -> 4x (expm + parallel scan + C proj)
//                -> output GEMM [4096,256]x[256,32000]
// Round 1: all-fp32 SIMT baseline. Parallel scan via Hillis-Steele with
// matrix-power weights (repeated squaring of Ad).
// ---------------------------------------------------------------------------

#define GF_ADDI      1   // C += I (square matrices)
#define GF_ALPHA_ROW 2   // alpha = alphaRow[(row>>10)*4 + awIdx]
#define GF_BETA1     4   // C += existing C
#define GF_BIAS      8   // C += bias[col]

// -------- static scratch (no allocations allowed) --------
__device__ float g_xe  [4 * 1024 * 256];   // embedded tokens
__device__ float g_pre [4 * 1024 * 256];   // weighted-sum accumulator
__device__ float g_u   [4 * 1024 * 512];   // scan ping
__device__ float g_v   [4 * 1024 * 512];   // scan pong
__device__ float g_P   [512 * 512];        // expm / power buffer A
__device__ float g_Q   [512 * 512];        // expm / power buffer B
__device__ float g_mean[4 * 256];
__device__ float g_w   [4 * 4];

// ---------------------------------------------------------------------------
__global__ void k_embed(const int* __restrict__ x, const float* __restrict__ emb,
                        float* __restrict__ xe) {
    int r = blockIdx.x;          // 0..4095
    int d = threadIdx.x;         // 0..63 (float4 lanes)
    int tok = x[r];
    reinterpret_cast<float4*>(xe)[(size_t)r * 64 + d] =
        reinterpret_cast<const float4*>(emb)[(size_t)tok * 64 + d];
}

__global__ void k_mean(const float* __restrict__ xe, float* __restrict__ mean) {
    int b = blockIdx.x, d = threadIdx.x;  // 4 blocks x 256 threads
    const float* p = xe + (size_t)b * 1024 * 256 + d;
    float s = 0.f;
    for (int t = 0; t < 1024; t++) s += p[(size_t)t * 256];
    mean[b * 256 + d] = s * (1.0f / 1024.0f);
}

__global__ void k_router(const float* __restrict__ mean,
                         const float* __restrict__ rw1, const float* __restrict__ rb1,
                         const float* __restrict__ rw2, const float* __restrict__ rb2,
                         float* __restrict__ w) {
    __shared__ float hid[4][64];
    __shared__ float logit[4][4];
    int j = threadIdx.x;  // 64 threads
    for (int b = 0; b < 4; b++) {
        float s = rb1[j];
        for (int d = 0; d < 256; d++) s = fmaf(mean[b * 256 + d], rw1[d * 64 + j], s);
        hid[b][j] = fmaxf(s, 0.f);
    }
    __syncthreads();
    if (j < 16) {
        int b = j >> 2, i = j & 3;
        float s = rb2[i];
        for (int k = 0; k < 64; k++) s = fmaf(hid[b][k], rw2[k * 4 + i], s);
        logit[b][i] = s;
    }
    __syncthreads();
    if (j < 4) {
        int b = j;
        float mx = -1e30f;
        for (int i = 0; i < 4; i++) mx = fmaxf(mx, logit[b][i]);
        float e[4], se = 0.f;
        for (int i = 0; i < 4; i++) { e[i] = __expf(logit[b][i] - mx); se += e[i]; }
        for (int i = 0; i < 4; i++) w[b * 4 + i] = e[i] / se;
    }
}

// pre[r,d] = xe[r,d] * sum_i w[b,i] * D_i[d]   (initializes the accumulator)
__global__ void k_dterm(const float* __restrict__ xe, const float* __restrict__ w,
                        const float* __restrict__ D0, const float* __restrict__ D1,
                        const float* __restrict__ D2, const float* __restrict__ D3,
                        float* __restrict__ pre) {
    int r = blockIdx.x, d = threadIdx.x;
    int b = r >> 10;
    float wd = w[b * 4 + 0] * D0[d] + w[b * 4 + 1] * D1[d]
             + w[b * 4 + 2] * D2[d] + w[b * 4 + 3] * D3[d];
    size_t idx = (size_t)r * 256 + d;
    pre[idx] = xe[idx] * wd;
}

__global__ void k_identity(float* __restrict__ P, int n) {
    int i = blockIdx.x * blockDim.x + threadIdx.x;
    if (i < n * n) P[i] = (i / n == i % n) ? 1.0f : 0.0f;
}

// ---------------------------------------------------------------------------
// Generic fp32 GEMM: C = f(alpha * A[MxK] @ B[KxN]).  M,N mult of 64, K mult of 16.
// ---------------------------------------------------------------------------
__global__ void k_gemm(const float* __restrict__ A, const float* __restrict__ B,
                       float* __restrict__ C, int M, int N, int K,
                       float alpha, int flags,
                       const float* __restrict__ alphaRow, int awIdx,
                       const float* __restrict__ bias) {
    __shared__ float As[16][65];
    __shared__ float Bs[16][64];
    int n0 = blockIdx.x * 64;
    int m0 = blockIdx.y * 64;
    int t = threadIdx.x;          // 256
    int tx = t & 15, ty = t >> 4;
    float acc[4][4] = {};
    for (int kt = 0; kt < K; kt += 16) {
        #pragma unroll
        for (int i = 0; i < 4; i++) {
            int e = t + i * 256;
            int m = e >> 4, k = e & 15;
            As[k][m] = A[(size_t)(m0 + m) * K + kt + k];
        }
        #pragma unroll
        for (int i = 0; i < 4; i++) {
            int e = t + i * 256;
            int k = e >> 6, n = e & 63;
            Bs[k][n] = B[(size_t)(kt + k) * N + n0 + n];
        }
        __syncthreads();
        #pragma unroll
        for (int k = 0; k < 16; k++) {
            float a[4], b[4];
            #pragma unroll
            for (int i = 0; i < 4; i++) a[i] = As[k][ty * 4 + i];
            #pragma unroll
            for (int j = 0; j < 4; j++) b[j] = Bs[k][tx * 4 + j];
            #pragma unroll
            for (int i = 0; i < 4; i++)
                #pragma unroll
                for (int j = 0; j < 4; j++)
                    acc[i][j] = fmaf(a[i], b[j], acc[i][j]);
        }
        __syncthreads();
    }
    #pragma unroll
    for (int i = 0; i < 4; i++) {
        int r = m0 + ty * 4 + i;
        float a = (flags & GF_ALPHA_ROW) ? alphaRow[(r >> 10) * 4 + awIdx] : alpha;
        #pragma unroll
        for (int j = 0; j < 4; j++) {
            int c = n0 + tx * 4 + j;
            float v = a * acc[i][j];
            if ((flags & GF_ADDI) && r == c) v += 1.0f;
            size_t idx = (size_t)r * N + c;
            if (flags & GF_BETA1) v += C[idx];
            if (flags & GF_BIAS) v += bias[c];
            C[idx] = v;
        }
    }
}

// ---------------------------------------------------------------------------
// One Hillis-Steele scan level: dst[t] = src[t] + (pos>=off ? src[t-off]@P : 0)
// src/dst: [4096, ds]; P: [ds, ds]; pos = row & 1023 (per-sequence position).
// ---------------------------------------------------------------------------
__global__ void k_scanlevel(const float* __restrict__ src, const float* __restrict__ P,
                            float* __restrict__ dst, int N, int off) {
    int n0 = blockIdx.x * 64;
    int m0 = blockIdx.y * 64;
    int p0 = m0 & 1023;
    int t = threadIdx.x;
    if (p0 + 63 < off) {   // whole block is pure copy
        #pragma unroll
        for (int i = 0; i < 16; i++) {
            int e = t + i * 256;
            int m = e >> 6, n = e & 63;
            size_t idx = (size_t)(m0 + m) * N + n0 + n;
            dst[idx] = src[idx];
        }
        return;
    }
    __shared__ float As[16][65];
    __shared__ float Bs[16][64];
    int tx = t & 15, ty = t >> 4;
    float acc[4][4] = {};
    for (int kt = 0; kt < N; kt += 16) {
        #pragma unroll
        for (int i = 0; i < 4; i++) {
            int e = t + i * 256;
            int m = e >> 4, k = e & 15;
            int rA = m0 + m - off; if (rA < 0) rA = 0;
            As[k][m] = src[(size_t)rA * N + kt + k];
        }
        #pragma unroll
        for (int i = 0; i < 4; i++) {
            int e = t + i * 256;
            int k = e >> 6, n = e & 63;
            Bs[k][n] = P[(size_t)(kt + k) * N + n0 + n];
        }
        __syncthreads();
        #pragma unroll
        for (int k = 0; k < 16; k++) {
            float a[4], b[4];
            #pragma unroll
            for (int i = 0; i < 4; i++) a[i] = As[k][ty * 4 + i];
            #pragma unroll
            for (int j = 0; j < 4; j++) b[j] = Bs[k][tx * 4 + j];
            #pragma unroll
            for (int i = 0; i < 4; i++)
                #pragma unroll
                for (int j = 0; j < 4; j++)
                    acc[i][j] = fmaf(a[i], b[j], acc[i][j]);
        }
        __syncthreads();
    }
    #pragma unroll
    for (int i = 0; i < 4; i++) {
        int r = m0 + ty * 4 + i;
        int pos = r & 1023;
        #pragma unroll
        for (int j = 0; j < 4; j++) {
            int c = n0 + tx * 4 + j;
            size_t idx = (size_t)r * N + c;
            float v = src[idx];
            if (pos >= off) v += acc[i][j];
            dst[idx] = v;
        }
    }
}

// ---------------------------------------------------------------------------
extern "C" void kernel_launch(void* const* d_in, const int* in_sizes, int n_in,
                              void* d_out, int out_size) {
    const int*   x    = (const int*)  d_in[0];
    const float* emb  = (const float*)d_in[1];
    const float* Am[4] = {(const float*)d_in[2],  (const float*)d_in[6],
                          (const float*)d_in[10], (const float*)d_in[14]};
    const float* Bm[4] = {(const float*)d_in[3],  (const float*)d_in[7],
                          (const float*)d_in[11], (const float*)d_in[15]};
    const float* Cm[4] = {(const float*)d_in[4],  (const float*)d_in[8],
                          (const float*)d_in[12], (const float*)d_in[16]};
    const float* Dm[4] = {(const float*)d_in[5],  (const float*)d_in[9],
                          (const float*)d_in[13], (const float*)d_in[17]};
    const float* rw1 = (const float*)d_in[18];
    const float* rb1 = (const float*)d_in[19];
    const float* rw2 = (const float*)d_in[20];
    const float* rb2 = (const float*)d_in[21];
    const float* ow  = (const float*)d_in[22];
    const float* ob  = (const float*)d_in[23];
    float* out = (float*)d_out;

    float *xe, *pre, *ub, *vb, *Pb, *Qb, *meanb, *wb;
    cudaGetSymbolAddress((void**)&xe,    g_xe);
    cudaGetSymbolAddress((void**)&pre,   g_pre);
    cudaGetSymbolAddress((void**)&ub,    g_u);
    cudaGetSymbolAddress((void**)&vb,    g_v);
    cudaGetSymbolAddress((void**)&Pb,    g_P);
    cudaGetSymbolAddress((void**)&Qb,    g_Q);
    cudaGetSymbolAddress((void**)&meanb, g_mean);
    cudaGetSymbolAddress((void**)&wb,    g_w);

    const int STATES[4] = {64, 128, 256, 512};

    // 1. embedding gather
    k_embed<<<4096, 64>>>(x, emb, xe);
    // 2. router
    k_mean<<<4, 256>>>(xe, meanb);
    k_router<<<1, 64>>>(meanb, rw1, rb1, rw2, rb2, wb);
    // 3. init accumulator with the (sum_i w_i * D_i) * xe term
    k_dterm<<<4096, 256>>>(xe, wb, Dm[0], Dm[1], Dm[2], Dm[3], pre);

    // 4. per-world SSM
    for (int i = 0; i < 4; i++) {
        int ds = STATES[i];
        dim3 gSq(ds / 64, ds / 64);

        // expm(0.1*A) via order-8 Horner Taylor: P <- I; P <- I + (0.1/k) A P
        k_identity<<<(ds * ds + 255) / 256, 256>>>(Pb, ds);
        float* cur = Pb; float* oth = Qb;
        for (int k = 8; k >= 1; k--) {
            k_gemm<<<gSq, 256>>>(Am[i], cur, oth, ds, ds, ds,
                                 0.1f / (float)k, GF_ADDI, nullptr, 0, nullptr);
            float* tmp = cur; cur = oth; oth = tmp;
        }
        // Ad now in `cur` (8 swaps -> back in Pb)

        // u = xe @ B_i   [4096, ds]
        k_gemm<<<dim3(ds / 64, 64), 256>>>(xe, Bm[i], ub, 4096, ds, 256,
                                           1.0f, 0, nullptr, 0, nullptr);

        // Hillis-Steele scan with matrix powers (10 levels)
        float* scur = ub; float* snxt = vb;
        float* pw = cur; float* pwo = oth;
        for (int l = 0; l < 10; l++) {
            k_scanlevel<<<dim3(ds / 64, 64), 256>>>(scur, pw, snxt, ds, 1 << l);
            { float* tmp = scur; scur = snxt; snxt = tmp; }
            if (l < 9) {
                k_gemm<<<gSq, 256>>>(pw, pw, pwo, ds, ds, ds,
                                     1.0f, 0, nullptr, 0, nullptr);
                float* tmp = pw; pw = pwo; pwo = tmp;
            }
        }
        // h in scur (== ub after 10 swaps)

        // pre += w[b,i] * (h @ C_i)
        k_gemm<<<dim3(256 / 64, 64), 256>>>(scur, Cm[i], pre, 4096, 256, ds,
                                            0.0f, GF_ALPHA_ROW | GF_BETA1, wb, i, nullptr);
    }

    // 5. out = pre @ ow + ob   [4096, 32000]
    k_gemm<<<dim3(32000 / 64, 4096 / 64), 256>>>(pre, ow, out, 4096, 32000, 256,
                                                 1.0f, GF_BIAS, nullptr, 0, ob);
    (void)in_sizes; (void)n_in; (void)out_size;
}

// round 6
// speedup vs baseline: 1.0035x; 1.0035x over previous
#include <cuda_runtime.h>
#include <cuda_bf16.h>
#include <cstdint>

// ---------------------------------------------------------------------------
// MultiWorldSSM: emb-gather -> router -> 4x (expm + parallel scan + C proj)
//                -> output GEMM [4096,256]x[256,32000]
// Round 1: all-fp32 SIMT baseline. Parallel scan via Hillis-Steele with
// matrix-power weights (repeated squaring of Ad).
// ---------------------------------------------------------------------------

#define GF_ADDI      1   // C += I (square matrices)
#define GF_ALPHA_ROW 2   // alpha = alphaRow[(row>>10)*4 + awIdx]
#define GF_BETA1     4   // C += existing C
#define GF_BIAS      8   // C += bias[col]

// -------- static scratch (no allocations allowed) --------
__device__ float g_xe  [4 * 1024 * 256];   // embedded tokens
__device__ float g_pre [4 * 1024 * 256];   // weighted-sum accumulator
__device__ float g_u   [4 * 1024 * 512];   // scan ping
__device__ float g_v   [4 * 1024 * 512];   // scan pong
__device__ float g_P   [512 * 512];        // expm / power buffer A
__device__ float g_Q   [512 * 512];        // expm / power buffer B
__device__ float g_mean[4 * 256];
__device__ float g_w   [4 * 4];

// ---------------------------------------------------------------------------
__global__ void k_embed(const int* __restrict__ x, const float* __restrict__ emb,
                        float* __restrict__ xe) {
    int r = blockIdx.x;          // 0..4095
    int d = threadIdx.x;         // 0..63 (float4 lanes)
    int tok = x[r];
    reinterpret_cast<float4*>(xe)[(size_t)r * 64 + d] =
        reinterpret_cast<const float4*>(emb)[(size_t)tok * 64 + d];
}

__global__ void k_mean(const float* __restrict__ xe, float* __restrict__ mean) {
    int b = blockIdx.x, d = threadIdx.x;  // 4 blocks x 256 threads
    const float* p = xe + (size_t)b * 1024 * 256 + d;
    float s = 0.f;
    for (int t = 0; t < 1024; t++) s += p[(size_t)t * 256];
    mean[b * 256 + d] = s * (1.0f / 1024.0f);
}

__global__ void k_router(const float* __restrict__ mean,
                         const float* __restrict__ rw1, const float* __restrict__ rb1,
                         const float* __restrict__ rw2, const float* __restrict__ rb2,
                         float* __restrict__ w) {
    __shared__ float hid[4][64];
    __shared__ float logit[4][4];
    int j = threadIdx.x;  // 64 threads
    for (int b = 0; b < 4; b++) {
        float s = rb1[j];
        for (int d = 0; d < 256; d++) s = fmaf(mean[b * 256 + d], rw1[d * 64 + j], s);
        hid[b][j] = fmaxf(s, 0.f);
    }
    __syncthreads();
    if (j < 16) {
        int b = j >> 2, i = j & 3;
        float s = rb2[i];
        for (int k = 0; k < 64; k++) s = fmaf(hid[b][k], rw2[k * 4 + i], s);
        logit[b][i] = s;
    }
    __syncthreads();
    if (j < 4) {
        int b = j;
        float mx = -1e30f;
        for (int i = 0; i < 4; i++) mx = fmaxf(mx, logit[b][i]);
        float e[4], se = 0.f;
        for (int i = 0; i < 4; i++) { e[i] = __expf(logit[b][i] - mx); se += e[i]; }
        for (int i = 0; i < 4; i++) w[b * 4 + i] = e[i] / se;
    }
}

// pre[r,d] = xe[r,d] * sum_i w[b,i] * D_i[d]   (initializes the accumulator)
__global__ void k_dterm(const float* __restrict__ xe, const float* __restrict__ w,
                        const float* __restrict__ D0, const float* __restrict__ D1,
                        const float* __restrict__ D2, const float* __restrict__ D3,
                        float* __restrict__ pre) {
    int r = blockIdx.x, d = threadIdx.x;
    int b = r >> 10;
    float wd = w[b * 4 + 0] * D0[d] + w[b * 4 + 1] * D1[d]
             + w[b * 4 + 2] * D2[d] + w[b * 4 + 3] * D3[d];
    size_t idx = (size_t)r * 256 + d;
    pre[idx] = xe[idx] * wd;
}

__global__ void k_identity(float* __restrict__ P, int n) {
    int i = blockIdx.x * blockDim.x + threadIdx.x;
    if (i < n * n) P[i] = (i / n == i % n) ? 1.0f : 0.0f;
}

// ---------------------------------------------------------------------------
// Generic fp32 GEMM: C = f(alpha * A[MxK] @ B[KxN]).  M,N mult of 64, K mult of 16.
// ---------------------------------------------------------------------------
__global__ void k_gemm(const float* __restrict__ A, const float* __restrict__ B,
                       float* __restrict__ C, int M, int N, int K,
                       float alpha, int flags,
                       const float* __restrict__ alphaRow, int awIdx,
                       const float* __restrict__ bias) {
    __shared__ float As[16][65];
    __shared__ float Bs[16][64];
    int n0 = blockIdx.x * 64;
    int m0 = blockIdx.y * 64;
    int t = threadIdx.x;          // 256
    int tx = t & 15, ty = t >> 4;
    float acc[4][4] = {};
    for (int kt = 0; kt < K; kt += 16) {
        #pragma unroll
        for (int i = 0; i < 4; i++) {
            int e = t + i * 256;
            int m = e >> 4, k = e & 15;
            As[k][m] = A[(size_t)(m0 + m) * K + kt + k];
        }
        #pragma unroll
        for (int i = 0; i < 4; i++) {
            int e = t + i * 256;
            int k = e >> 6, n = e & 63;
            Bs[k][n] = B[(size_t)(kt + k) * N + n0 + n];
        }
        __syncthreads();
        #pragma unroll
        for (int k = 0; k < 16; k++) {
            float a[4], b[4];
            #pragma unroll
            for (int i = 0; i < 4; i++) a[i] = As[k][ty * 4 + i];
            #pragma unroll
            for (int j = 0; j < 4; j++) b[j] = Bs[k][tx * 4 + j];
            #pragma unroll
            for (int i = 0; i < 4; i++)
                #pragma unroll
                for (int j = 0; j < 4; j++)
                    acc[i][j] = fmaf(a[i], b[j], acc[i][j]);
        }
        __syncthreads();
    }
    #pragma unroll
    for (int i = 0; i < 4; i++) {
        int r = m0 + ty * 4 + i;
        float a = (flags & GF_ALPHA_ROW) ? alphaRow[(r >> 10) * 4 + awIdx] : alpha;
        #pragma unroll
        for (int j = 0; j < 4; j++) {
            int c = n0 + tx * 4 + j;
            float v = a * acc[i][j];
            if ((flags & GF_ADDI) && r == c) v += 1.0f;
            size_t idx = (size_t)r * N + c;
            if (flags & GF_BETA1) v += C[idx];
            if (flags & GF_BIAS) v += bias[c];
            C[idx] = v;
        }
    }
}

// ---------------------------------------------------------------------------
// One Hillis-Steele scan level: dst[t] = src[t] + (pos>=off ? src[t-off]@P : 0)
// src/dst: [4096, ds]; P: [ds, ds]; pos = row & 1023 (per-sequence position).
// ---------------------------------------------------------------------------
__global__ void k_scanlevel(const float* __restrict__ src, const float* __restrict__ P,
                            float* __restrict__ dst, int N, int off) {
    int n0 = blockIdx.x * 64;
    int m0 = blockIdx.y * 64;
    int p0 = m0 & 1023;
    int t = threadIdx.x;
    if (p0 + 63 < off) {   // whole block is pure copy
        #pragma unroll
        for (int i = 0; i < 16; i++) {
            int e = t + i * 256;
            int m = e >> 6, n = e & 63;
            size_t idx = (size_t)(m0 + m) * N + n0 + n;
            dst[idx] = src[idx];
        }
        return;
    }
    __shared__ float As[16][65];
    __shared__ float Bs[16][64];
    int tx = t & 15, ty = t >> 4;
    float acc[4][4] = {};
    for (int kt = 0; kt < N; kt += 16) {
        #pragma unroll
        for (int i = 0; i < 4; i++) {
            int e = t + i * 256;
            int m = e >> 4, k = e & 15;
            int rA = m0 + m - off; if (rA < 0) rA = 0;
            As[k][m] = src[(size_t)rA * N + kt + k];
        }
        #pragma unroll
        for (int i = 0; i < 4; i++) {
            int e = t + i * 256;
            int k = e >> 6, n = e & 63;
            Bs[k][n] = P[(size_t)(kt + k) * N + n0 + n];
        }
        __syncthreads();
        #pragma unroll
        for (int k = 0; k < 16; k++) {
            float a[4], b[4];
            #pragma unroll
            for (int i = 0; i < 4; i++) a[i] = As[k][ty * 4 + i];
            #pragma unroll
            for (int j = 0; j < 4; j++) b[j] = Bs[k][tx * 4 + j];
            #pragma unroll
            for (int i = 0; i < 4; i++)
                #pragma unroll
                for (int j = 0; j < 4; j++)
                    acc[i][j] = fmaf(a[i], b[j], acc[i][j]);
        }
        __syncthreads();
    }
    #pragma unroll
    for (int i = 0; i < 4; i++) {
        int r = m0 + ty * 4 + i;
        int pos = r & 1023;
        #pragma unroll
        for (int j = 0; j < 4; j++) {
            int c = n0 + tx * 4 + j;
            size_t idx = (size_t)r * N + c;
            float v = src[idx];
            if (pos >= off) v += acc[i][j];
            dst[idx] = v;
        }
    }
}

// ---------------------------------------------------------------------------
extern "C" void kernel_launch(void* const* d_in, const int* in_sizes, int n_in,
                              void* d_out, int out_size) {
    const int*   x    = (const int*)  d_in[0];
    const float* emb  = (const float*)d_in[1];
    const float* Am[4] = {(const float*)d_in[2],  (const float*)d_in[6],
                          (const float*)d_in[10], (const float*)d_in[14]};
    const float* Bm[4] = {(const float*)d_in[3],  (const float*)d_in[7],
                          (const float*)d_in[11], (const float*)d_in[15]};
    const float* Cm[4] = {(const float*)d_in[4],  (const float*)d_in[8],
                          (const float*)d_in[12], (const float*)d_in[16]};
    const float* Dm[4] = {(const float*)d_in[5],  (const float*)d_in[9],
                          (const float*)d_in[13], (const float*)d_in[17]};
    const float* rw1 = (const float*)d_in[18];
    const float* rb1 = (const float*)d_in[19];
    const float* rw2 = (const float*)d_in[20];
    const float* rb2 = (const float*)d_in[21];
    const float* ow  = (const float*)d_in[22];
    const float* ob  = (const float*)d_in[23];
    float* out = (float*)d_out;

    float *xe, *pre, *ub, *vb, *Pb, *Qb, *meanb, *wb;
    cudaGetSymbolAddress((void**)&xe,    g_xe);
    cudaGetSymbolAddress((void**)&pre,   g_pre);
    cudaGetSymbolAddress((void**)&ub,    g_u);
    cudaGetSymbolAddress((void**)&vb,    g_v);
    cudaGetSymbolAddress((void**)&Pb,    g_P);
    cudaGetSymbolAddress((void**)&Qb,    g_Q);
    cudaGetSymbolAddress((void**)&meanb, g_mean);
    cudaGetSymbolAddress((void**)&wb,    g_w);

    const int STATES[4] = {64, 128, 256, 512};

    // 1. embedding gather
    k_embed<<<4096, 64>>>(x, emb, xe);
    // 2. router
    k_mean<<<4, 256>>>(xe, meanb);
    k_router<<<1, 64>>>(meanb, rw1, rb1, rw2, rb2, wb);
    // 3. init accumulator with the (sum_i w_i * D_i) * xe term
    k_dterm<<<4096, 256>>>(xe, wb, Dm[0], Dm[1], Dm[2], Dm[3], pre);

    // 4. per-world SSM
    for (int i = 0; i < 4; i++) {
        int ds = STATES[i];
        dim3 gSq(ds / 64, ds / 64);

        // expm(0.1*A) via order-8 Horner Taylor: P <- I; P <- I + (0.1/k) A P
        k_identity<<<(ds * ds + 255) / 256, 256>>>(Pb, ds);
        float* cur = Pb; float* oth = Qb;
        for (int k = 8; k >= 1; k--) {
            k_gemm<<<gSq, 256>>>(Am[i], cur, oth, ds, ds, ds,
                                 0.1f / (float)k, GF_ADDI, nullptr, 0, nullptr);
            float* tmp = cur; cur = oth; oth = tmp;
        }
        // Ad now in `cur` (8 swaps -> back in Pb)

        // u = xe @ B_i   [4096, ds]
        k_gemm<<<dim3(ds / 64, 64), 256>>>(xe, Bm[i], ub, 4096, ds, 256,
                                           1.0f, 0, nullptr, 0, nullptr);

        // Hillis-Steele scan with matrix powers (10 levels)
        float* scur = ub; float* snxt = vb;
        float* pw = cur; float* pwo = oth;
        for (int l = 0; l < 10; l++) {
            k_scanlevel<<<dim3(ds / 64, 64), 256>>>(scur, pw, snxt, ds, 1 << l);
            { float* tmp = scur; scur = snxt; snxt = tmp; }
            if (l < 9) {
                k_gemm<<<gSq, 256>>>(pw, pw, pwo, ds, ds, ds,
                                     1.0f, 0, nullptr, 0, nullptr);
                float* tmp = pw; pw = pwo; pwo = tmp;
            }
        }
        // h in scur (== ub after 10 swaps)

        // pre += w[b,i] * (h @ C_i)
        k_gemm<<<dim3(256 / 64, 64), 256>>>(scur, Cm[i], pre, 4096, 256, ds,
                                            0.0f, GF_ALPHA_ROW | GF_BETA1, wb, i, nullptr);
    }

    // 5. out = pre @ ow + ob   [4096, 32000]
    k_gemm<<<dim3(32000 / 64, 4096 / 64), 256>>>(pre, ow, out, 4096, 32000, 256,
                                                 1.0f, GF_BIAS, nullptr, 0, ob);
    (void)in_sizes; (void)n_in; (void)out_size;
}

// round 7
// speedup vs baseline: 1.0048x; 1.0012x over previous
#include <cuda_runtime.h>
#include <cuda_bf16.h>
#include <cstdint>

// ---------------------------------------------------------------------------
// MultiWorldSSM: emb-gather -> router -> 4x (expm + parallel scan + C proj)
//                -> output GEMM [4096,256]x[256,32000]
// Round 1: all-fp32 SIMT baseline. Parallel scan via Hillis-Steele with
// matrix-power weights (repeated squaring of Ad).
// ---------------------------------------------------------------------------

#define GF_ADDI      1   // C += I (square matrices)
#define GF_ALPHA_ROW 2   // alpha = alphaRow[(row>>10)*4 + awIdx]
#define GF_BETA1     4   // C += existing C
#define GF_BIAS      8   // C += bias[col]

// -------- static scratch (no allocations allowed) --------
__device__ float g_xe  [4 * 1024 * 256];   // embedded tokens
__device__ float g_pre [4 * 1024 * 256];   // weighted-sum accumulator
__device__ float g_u   [4 * 1024 * 512];   // scan ping
__device__ float g_v   [4 * 1024 * 512];   // scan pong
__device__ float g_P   [512 * 512];        // expm / power buffer A
__device__ float g_Q   [512 * 512];        // expm / power buffer B
__device__ float g_mean[4 * 256];
__device__ float g_w   [4 * 4];

// ---------------------------------------------------------------------------
__global__ void k_embed(const int* __restrict__ x, const float* __restrict__ emb,
                        float* __restrict__ xe) {
    int r = blockIdx.x;          // 0..4095
    int d = threadIdx.x;         // 0..63 (float4 lanes)
    int tok = x[r];
    reinterpret_cast<float4*>(xe)[(size_t)r * 64 + d] =
        reinterpret_cast<const float4*>(emb)[(size_t)tok * 64 + d];
}

__global__ void k_mean(const float* __restrict__ xe, float* __restrict__ mean) {
    int b = blockIdx.x, d = threadIdx.x;  // 4 blocks x 256 threads
    const float* p = xe + (size_t)b * 1024 * 256 + d;
    float s = 0.f;
    for (int t = 0; t < 1024; t++) s += p[(size_t)t * 256];
    mean[b * 256 + d] = s * (1.0f / 1024.0f);
}

__global__ void k_router(const float* __restrict__ mean,
                         const float* __restrict__ rw1, const float* __restrict__ rb1,
                         const float* __restrict__ rw2, const float* __restrict__ rb2,
                         float* __restrict__ w) {
    __shared__ float hid[4][64];
    __shared__ float logit[4][4];
    int j = threadIdx.x;  // 64 threads
    for (int b = 0; b < 4; b++) {
        float s = rb1[j];
        for (int d = 0; d < 256; d++) s = fmaf(mean[b * 256 + d], rw1[d * 64 + j], s);
        hid[b][j] = fmaxf(s, 0.f);
    }
    __syncthreads();
    if (j < 16) {
        int b = j >> 2, i = j & 3;
        float s = rb2[i];
        for (int k = 0; k < 64; k++) s = fmaf(hid[b][k], rw2[k * 4 + i], s);
        logit[b][i] = s;
    }
    __syncthreads();
    if (j < 4) {
        int b = j;
        float mx = -1e30f;
        for (int i = 0; i < 4; i++) mx = fmaxf(mx, logit[b][i]);
        float e[4], se = 0.f;
        for (int i = 0; i < 4; i++) { e[i] = __expf(logit[b][i] - mx); se += e[i]; }
        for (int i = 0; i < 4; i++) w[b * 4 + i] = e[i] / se;
    }
}

// pre[r,d] = xe[r,d] * sum_i w[b,i] * D_i[d]   (initializes the accumulator)
__global__ void k_dterm(const float* __restrict__ xe, const float* __restrict__ w,
                        const float* __restrict__ D0, const float* __restrict__ D1,
                        const float* __restrict__ D2, const float* __restrict__ D3,
                        float* __restrict__ pre) {
    int r = blockIdx.x, d = threadIdx.x;
    int b = r >> 10;
    float wd = w[b * 4 + 0] * D0[d] + w[b * 4 + 1] * D1[d]
             + w[b * 4 + 2] * D2[d] + w[b * 4 + 3] * D3[d];
    size_t idx = (size_t)r * 256 + d;
    pre[idx] = xe[idx] * wd;
}

__global__ void k_identity(float* __restrict__ P, int n) {
    int i = blockIdx.x * blockDim.x + threadIdx.x;
    if (i < n * n) P[i] = (i / n == i % n) ? 1.0f : 0.0f;
}

// ---------------------------------------------------------------------------
// Generic fp32 GEMM: C = f(alpha * A[MxK] @ B[KxN]).  M,N mult of 64, K mult of 16.
// ---------------------------------------------------------------------------
__global__ void k_gemm(const float* __restrict__ A, const float* __restrict__ B,
                       float* __restrict__ C, int M, int N, int K,
                       float alpha, int flags,
                       const float* __restrict__ alphaRow, int awIdx,
                       const float* __restrict__ bias) {
    __shared__ float As[16][65];
    __shared__ float Bs[16][64];
    int n0 = blockIdx.x * 64;
    int m0 = blockIdx.y * 64;
    int t = threadIdx.x;          // 256
    int tx = t & 15, ty = t >> 4;
    float acc[4][4] = {};
    for (int kt = 0; kt < K; kt += 16) {
        #pragma unroll
        for (int i = 0; i < 4; i++) {
            int e = t + i * 256;
            int m = e >> 4, k = e & 15;
            As[k][m] = A[(size_t)(m0 + m) * K + kt + k];
        }
        #pragma unroll
        for (int i = 0; i < 4; i++) {
            int e = t + i * 256;
            int k = e >> 6, n = e & 63;
            Bs[k][n] = B[(size_t)(kt + k) * N + n0 + n];
        }
        __syncthreads();
        #pragma unroll
        for (int k = 0; k < 16; k++) {
            float a[4], b[4];
            #pragma unroll
            for (int i = 0; i < 4; i++) a[i] = As[k][ty * 4 + i];
            #pragma unroll
            for (int j = 0; j < 4; j++) b[j] = Bs[k][tx * 4 + j];
            #pragma unroll
            for (int i = 0; i < 4; i++)
                #pragma unroll
                for (int j = 0; j < 4; j++)
                    acc[i][j] = fmaf(a[i], b[j], acc[i][j]);
        }
        __syncthreads();
    }
    #pragma unroll
    for (int i = 0; i < 4; i++) {
        int r = m0 + ty * 4 + i;
        float a = (flags & GF_ALPHA_ROW) ? alphaRow[(r >> 10) * 4 + awIdx] : alpha;
        #pragma unroll
        for (int j = 0; j < 4; j++) {
            int c = n0 + tx * 4 + j;
            float v = a * acc[i][j];
            if ((flags & GF_ADDI) && r == c) v += 1.0f;
            size_t idx = (size_t)r * N + c;
            if (flags & GF_BETA1) v += C[idx];
            if (flags & GF_BIAS) v += bias[c];
            C[idx] = v;
        }
    }
}

// ---------------------------------------------------------------------------
// One Hillis-Steele scan level: dst[t] = src[t] + (pos>=off ? src[t-off]@P : 0)
// src/dst: [4096, ds]; P: [ds, ds]; pos = row & 1023 (per-sequence position).
// ---------------------------------------------------------------------------
__global__ void k_scanlevel(const float* __restrict__ src, const float* __restrict__ P,
                            float* __restrict__ dst, int N, int off) {
    int n0 = blockIdx.x * 64;
    int m0 = blockIdx.y * 64;
    int p0 = m0 & 1023;
    int t = threadIdx.x;
    if (p0 + 63 < off) {   // whole block is pure copy
        #pragma unroll
        for (int i = 0; i < 16; i++) {
            int e = t + i * 256;
            int m = e >> 6, n = e & 63;
            size_t idx = (size_t)(m0 + m) * N + n0 + n;
            dst[idx] = src[idx];
        }
        return;
    }
    __shared__ float As[16][65];
    __shared__ float Bs[16][64];
    int tx = t & 15, ty = t >> 4;
    float acc[4][4] = {};
    for (int kt = 0; kt < N; kt += 16) {
        #pragma unroll
        for (int i = 0; i < 4; i++) {
            int e = t + i * 256;
            int m = e >> 4, k = e & 15;
            int rA = m0 + m - off; if (rA < 0) rA = 0;
            As[k][m] = src[(size_t)rA * N + kt + k];
        }
        #pragma unroll
        for (int i = 0; i < 4; i++) {
            int e = t + i * 256;
            int k = e >> 6, n = e & 63;
            Bs[k][n] = P[(size_t)(kt + k) * N + n0 + n];
        }
        __syncthreads();
        #pragma unroll
        for (int k = 0; k < 16; k++) {
            float a[4], b[4];
            #pragma unroll
            for (int i = 0; i < 4; i++) a[i] = As[k][ty * 4 + i];
            #pragma unroll
            for (int j = 0; j < 4; j++) b[j] = Bs[k][tx * 4 + j];
            #pragma unroll
            for (int i = 0; i < 4; i++)
                #pragma unroll
                for (int j = 0; j < 4; j++)
                    acc[i][j] = fmaf(a[i], b[j], acc[i][j]);
        }
        __syncthreads();
    }
    #pragma unroll
    for (int i = 0; i < 4; i++) {
        int r = m0 + ty * 4 + i;
        int pos = r & 1023;
        #pragma unroll
        for (int j = 0; j < 4; j++) {
            int c = n0 + tx * 4 + j;
            size_t idx = (size_t)r * N + c;
            float v = src[idx];
            if (pos >= off) v += acc[i][j];
            dst[idx] = v;
        }
    }
}

// ---------------------------------------------------------------------------
extern "C" void kernel_launch(void* const* d_in, const int* in_sizes, int n_in,
                              void* d_out, int out_size) {
    const int*   x    = (const int*)  d_in[0];
    const float* emb  = (const float*)d_in[1];
    const float* Am[4] = {(const float*)d_in[2],  (const float*)d_in[6],
                          (const float*)d_in[10], (const float*)d_in[14]};
    const float* Bm[4] = {(const float*)d_in[3],  (const float*)d_in[7],
                          (const float*)d_in[11], (const float*)d_in[15]};
    const float* Cm[4] = {(const float*)d_in[4],  (const float*)d_in[8],
                          (const float*)d_in[12], (const float*)d_in[16]};
    const float* Dm[4] = {(const float*)d_in[5],  (const float*)d_in[9],
                          (const float*)d_in[13], (const float*)d_in[17]};
    const float* rw1 = (const float*)d_in[18];
    const float* rb1 = (const float*)d_in[19];
    const float* rw2 = (const float*)d_in[20];
    const float* rb2 = (const float*)d_in[21];
    const float* ow  = (const float*)d_in[22];
    const float* ob  = (const float*)d_in[23];
    float* out = (float*)d_out;

    float *xe, *pre, *ub, *vb, *Pb, *Qb, *meanb, *wb;
    cudaGetSymbolAddress((void**)&xe,    g_xe);
    cudaGetSymbolAddress((void**)&pre,   g_pre);
    cudaGetSymbolAddress((void**)&ub,    g_u);
    cudaGetSymbolAddress((void**)&vb,    g_v);
    cudaGetSymbolAddress((void**)&Pb,    g_P);
    cudaGetSymbolAddress((void**)&Qb,    g_Q);
    cudaGetSymbolAddress((void**)&meanb, g_mean);
    cudaGetSymbolAddress((void**)&wb,    g_w);

    const int STATES[4] = {64, 128, 256, 512};

    // 1. embedding gather
    k_embed<<<4096, 64>>>(x, emb, xe);
    // 2. router
    k_mean<<<4, 256>>>(xe, meanb);
    k_router<<<1, 64>>>(meanb, rw1, rb1, rw2, rb2, wb);
    // 3. init accumulator with the (sum_i w_i * D_i) * xe term
    k_dterm<<<4096, 256>>>(xe, wb, Dm[0], Dm[1], Dm[2], Dm[3], pre);

    // 4. per-world SSM
    for (int i = 0; i < 4; i++) {
        int ds = STATES[i];
        dim3 gSq(ds / 64, ds / 64);

        // expm(0.1*A) via order-8 Horner Taylor: P <- I; P <- I + (0.1/k) A P
        k_identity<<<(ds * ds + 255) / 256, 256>>>(Pb, ds);
        float* cur = Pb; float* oth = Qb;
        for (int k = 8; k >= 1; k--) {
            k_gemm<<<gSq, 256>>>(Am[i], cur, oth, ds, ds, ds,
                                 0.1f / (float)k, GF_ADDI, nullptr, 0, nullptr);
            float* tmp = cur; cur = oth; oth = tmp;
        }
        // Ad now in `cur` (8 swaps -> back in Pb)

        // u = xe @ B_i   [4096, ds]
        k_gemm<<<dim3(ds / 64, 64), 256>>>(xe, Bm[i], ub, 4096, ds, 256,
                                           1.0f, 0, nullptr, 0, nullptr);

        // Hillis-Steele scan with matrix powers (10 levels)
        float* scur = ub; float* snxt = vb;
        float* pw = cur; float* pwo = oth;
        for (int l = 0; l < 10; l++) {
            k_scanlevel<<<dim3(ds / 64, 64), 256>>>(scur, pw, snxt, ds, 1 << l);
            { float* tmp = scur; scur = snxt; snxt = tmp; }
            if (l < 9) {
                k_gemm<<<gSq, 256>>>(pw, pw, pwo, ds, ds, ds,
                                     1.0f, 0, nullptr, 0, nullptr);
                float* tmp = pw; pw = pwo; pwo = tmp;
            }
        }
        // h in scur (== ub after 10 swaps)

        // pre += w[b,i] * (h @ C_i)
        k_gemm<<<dim3(256 / 64, 64), 256>>>(scur, Cm[i], pre, 4096, 256, ds,
                                            0.0f, GF_ALPHA_ROW | GF_BETA1, wb, i, nullptr);
    }

    // 5. out = pre @ ow + ob   [4096, 32000]
    k_gemm<<<dim3(32000 / 64, 4096 / 64), 256>>>(pre, ow, out, 4096, 32000, 256,
                                                 1.0f, GF_BIAS, nullptr, 0, ob);
    (void)in_sizes; (void)n_in; (void)out_size;
}

// round 9
// speedup vs baseline: 1.0065x; 1.0017x over previous
#include <cuda_runtime.h>
#include <cuda_bf16.h>
#include <cstdint>

// ---------------------------------------------------------------------------
// MultiWorldSSM: emb-gather -> router -> 4x (expm + parallel scan + C proj)
//                -> output GEMM [4096,256]x[256,32000]
// Round 1: all-fp32 SIMT baseline. Parallel scan via Hillis-Steele with
// matrix-power weights (repeated squaring of Ad).
// ---------------------------------------------------------------------------

#define GF_ADDI      1   // C += I (square matrices)
#define GF_ALPHA_ROW 2   // alpha = alphaRow[(row>>10)*4 + awIdx]
#define GF_BETA1     4   // C += existing C
#define GF_BIAS      8   // C += bias[col]

// -------- static scratch (no allocations allowed) --------
__device__ float g_xe  [4 * 1024 * 256];   // embedded tokens
__device__ float g_pre [4 * 1024 * 256];   // weighted-sum accumulator
__device__ float g_u   [4 * 1024 * 512];   // scan ping
__device__ float g_v   [4 * 1024 * 512];   // scan pong
__device__ float g_P   [512 * 512];        // expm / power buffer A
__device__ float g_Q   [512 * 512];        // expm / power buffer B
__device__ float g_mean[4 * 256];
__device__ float g_w   [4 * 4];

// ---------------------------------------------------------------------------
__global__ void k_embed(const int* __restrict__ x, const float* __restrict__ emb,
                        float* __restrict__ xe) {
    int r = blockIdx.x;          // 0..4095
    int d = threadIdx.x;         // 0..63 (float4 lanes)
    int tok = x[r];
    reinterpret_cast<float4*>(xe)[(size_t)r * 64 + d] =
        reinterpret_cast<const float4*>(emb)[(size_t)tok * 64 + d];
}

__global__ void k_mean(const float* __restrict__ xe, float* __restrict__ mean) {
    int b = blockIdx.x, d = threadIdx.x;  // 4 blocks x 256 threads
    const float* p = xe + (size_t)b * 1024 * 256 + d;
    float s = 0.f;
    for (int t = 0; t < 1024; t++) s += p[(size_t)t * 256];
    mean[b * 256 + d] = s * (1.0f / 1024.0f);
}

__global__ void k_router(const float* __restrict__ mean,
                         const float* __restrict__ rw1, const float* __restrict__ rb1,
                         const float* __restrict__ rw2, const float* __restrict__ rb2,
                         float* __restrict__ w) {
    __shared__ float hid[4][64];
    __shared__ float logit[4][4];
    int j = threadIdx.x;  // 64 threads
    for (int b = 0; b < 4; b++) {
        float s = rb1[j];
        for (int d = 0; d < 256; d++) s = fmaf(mean[b * 256 + d], rw1[d * 64 + j], s);
        hid[b][j] = fmaxf(s, 0.f);
    }
    __syncthreads();
    if (j < 16) {
        int b = j >> 2, i = j & 3;
        float s = rb2[i];
        for (int k = 0; k < 64; k++) s = fmaf(hid[b][k], rw2[k * 4 + i], s);
        logit[b][i] = s;
    }
    __syncthreads();
    if (j < 4) {
        int b = j;
        float mx = -1e30f;
        for (int i = 0; i < 4; i++) mx = fmaxf(mx, logit[b][i]);
        float e[4], se = 0.f;
        for (int i = 0; i < 4; i++) { e[i] = __expf(logit[b][i] - mx); se += e[i]; }
        for (int i = 0; i < 4; i++) w[b * 4 + i] = e[i] / se;
    }
}

// pre[r,d] = xe[r,d] * sum_i w[b,i] * D_i[d]   (initializes the accumulator)
__global__ void k_dterm(const float* __restrict__ xe, const float* __restrict__ w,
                        const float* __restrict__ D0, const float* __restrict__ D1,
                        const float* __restrict__ D2, const float* __restrict__ D3,
                        float* __restrict__ pre) {
    int r = blockIdx.x, d = threadIdx.x;
    int b = r >> 10;
    float wd = w[b * 4 + 0] * D0[d] + w[b * 4 + 1] * D1[d]
             + w[b * 4 + 2] * D2[d] + w[b * 4 + 3] * D3[d];
    size_t idx = (size_t)r * 256 + d;
    pre[idx] = xe[idx] * wd;
}

__global__ void k_identity(float* __restrict__ P, int n) {
    int i = blockIdx.x * blockDim.x + threadIdx.x;
    if (i < n * n) P[i] = (i / n == i % n) ? 1.0f : 0.0f;
}

// ---------------------------------------------------------------------------
// Generic fp32 GEMM: C = f(alpha * A[MxK] @ B[KxN]).  M,N mult of 64, K mult of 16.
// ---------------------------------------------------------------------------
__global__ void k_gemm(const float* __restrict__ A, const float* __restrict__ B,
                       float* __restrict__ C, int M, int N, int K,
                       float alpha, int flags,
                       const float* __restrict__ alphaRow, int awIdx,
                       const float* __restrict__ bias) {
    __shared__ float As[16][65];
    __shared__ float Bs[16][64];
    int n0 = blockIdx.x * 64;
    int m0 = blockIdx.y * 64;
    int t = threadIdx.x;          // 256
    int tx = t & 15, ty = t >> 4;
    float acc[4][4] = {};
    for (int kt = 0; kt < K; kt += 16) {
        #pragma unroll
        for (int i = 0; i < 4; i++) {
            int e = t + i * 256;
            int m = e >> 4, k = e & 15;
            As[k][m] = A[(size_t)(m0 + m) * K + kt + k];
        }
        #pragma unroll
        for (int i = 0; i < 4; i++) {
            int e = t + i * 256;
            int k = e >> 6, n = e & 63;
            Bs[k][n] = B[(size_t)(kt + k) * N + n0 + n];
        }
        __syncthreads();
        #pragma unroll
        for (int k = 0; k < 16; k++) {
            float a[4], b[4];
            #pragma unroll
            for (int i = 0; i < 4; i++) a[i] = As[k][ty * 4 + i];
            #pragma unroll
            for (int j = 0; j < 4; j++) b[j] = Bs[k][tx * 4 + j];
            #pragma unroll
            for (int i = 0; i < 4; i++)
                #pragma unroll
                for (int j = 0; j < 4; j++)
                    acc[i][j] = fmaf(a[i], b[j], acc[i][j]);
        }
        __syncthreads();
    }
    #pragma unroll
    for (int i = 0; i < 4; i++) {
        int r = m0 + ty * 4 + i;
        float a = (flags & GF_ALPHA_ROW) ? alphaRow[(r >> 10) * 4 + awIdx] : alpha;
        #pragma unroll
        for (int j = 0; j < 4; j++) {
            int c = n0 + tx * 4 + j;
            float v = a * acc[i][j];
            if ((flags & GF_ADDI) && r == c) v += 1.0f;
            size_t idx = (size_t)r * N + c;
            if (flags & GF_BETA1) v += C[idx];
            if (flags & GF_BIAS) v += bias[c];
            C[idx] = v;
        }
    }
}

// ---------------------------------------------------------------------------
// One Hillis-Steele scan level: dst[t] = src[t] + (pos>=off ? src[t-off]@P : 0)
// src/dst: [4096, ds]; P: [ds, ds]; pos = row & 1023 (per-sequence position).
// ---------------------------------------------------------------------------
__global__ void k_scanlevel(const float* __restrict__ src, const float* __restrict__ P,
                            float* __restrict__ dst, int N, int off) {
    int n0 = blockIdx.x * 64;
    int m0 = blockIdx.y * 64;
    int p0 = m0 & 1023;
    int t = threadIdx.x;
    if (p0 + 63 < off) {   // whole block is pure copy
        #pragma unroll
        for (int i = 0; i < 16; i++) {
            int e = t + i * 256;
            int m = e >> 6, n = e & 63;
            size_t idx = (size_t)(m0 + m) * N + n0 + n;
            dst[idx] = src[idx];
        }
        return;
    }
    __shared__ float As[16][65];
    __shared__ float Bs[16][64];
    int tx = t & 15, ty = t >> 4;
    float acc[4][4] = {};
    for (int kt = 0; kt < N; kt += 16) {
        #pragma unroll
        for (int i = 0; i < 4; i++) {
            int e = t + i * 256;
            int m = e >> 4, k = e & 15;
            int rA = m0 + m - off; if (rA < 0) rA = 0;
            As[k][m] = src[(size_t)rA * N + kt + k];
        }
        #pragma unroll
        for (int i = 0; i < 4; i++) {
            int e = t + i * 256;
            int k = e >> 6, n = e & 63;
            Bs[k][n] = P[(size_t)(kt + k) * N + n0 + n];
        }
        __syncthreads();
        #pragma unroll
        for (int k = 0; k < 16; k++) {
            float a[4], b[4];
            #pragma unroll
            for (int i = 0; i < 4; i++) a[i] = As[k][ty * 4 + i];
            #pragma unroll
            for (int j = 0; j < 4; j++) b[j] = Bs[k][tx * 4 + j];
            #pragma unroll
            for (int i = 0; i < 4; i++)
                #pragma unroll
                for (int j = 0; j < 4; j++)
                    acc[i][j] = fmaf(a[i], b[j], acc[i][j]);
        }
        __syncthreads();
    }
    #pragma unroll
    for (int i = 0; i < 4; i++) {
        int r = m0 + ty * 4 + i;
        int pos = r & 1023;
        #pragma unroll
        for (int j = 0; j < 4; j++) {
            int c = n0 + tx * 4 + j;
            size_t idx = (size_t)r * N + c;
            float v = src[idx];
            if (pos >= off) v += acc[i][j];
            dst[idx] = v;
        }
    }
}

// ---------------------------------------------------------------------------
extern "C" void kernel_launch(void* const* d_in, const int* in_sizes, int n_in,
                              void* d_out, int out_size) {
    const int*   x    = (const int*)  d_in[0];
    const float* emb  = (const float*)d_in[1];
    const float* Am[4] = {(const float*)d_in[2],  (const float*)d_in[6],
                          (const float*)d_in[10], (const float*)d_in[14]};
    const float* Bm[4] = {(const float*)d_in[3],  (const float*)d_in[7],
                          (const float*)d_in[11], (const float*)d_in[15]};
    const float* Cm[4] = {(const float*)d_in[4],  (const float*)d_in[8],
                          (const float*)d_in[12], (const float*)d_in[16]};
    const float* Dm[4] = {(const float*)d_in[5],  (const float*)d_in[9],
                          (const float*)d_in[13], (const float*)d_in[17]};
    const float* rw1 = (const float*)d_in[18];
    const float* rb1 = (const float*)d_in[19];
    const float* rw2 = (const float*)d_in[20];
    const float* rb2 = (const float*)d_in[21];
    const float* ow  = (const float*)d_in[22];
    const float* ob  = (const float*)d_in[23];
    float* out = (float*)d_out;

    float *xe, *pre, *ub, *vb, *Pb, *Qb, *meanb, *wb;
    cudaGetSymbolAddress((void**)&xe,    g_xe);
    cudaGetSymbolAddress((void**)&pre,   g_pre);
    cudaGetSymbolAddress((void**)&ub,    g_u);
    cudaGetSymbolAddress((void**)&vb,    g_v);
    cudaGetSymbolAddress((void**)&Pb,    g_P);
    cudaGetSymbolAddress((void**)&Qb,    g_Q);
    cudaGetSymbolAddress((void**)&meanb, g_mean);
    cudaGetSymbolAddress((void**)&wb,    g_w);

    const int STATES[4] = {64, 128, 256, 512};

    // 1. embedding gather
    k_embed<<<4096, 64>>>(x, emb, xe);
    // 2. router
    k_mean<<<4, 256>>>(xe, meanb);
    k_router<<<1, 64>>>(meanb, rw1, rb1, rw2, rb2, wb);
    // 3. init accumulator with the (sum_i w_i * D_i) * xe term
    k_dterm<<<4096, 256>>>(xe, wb, Dm[0], Dm[1], Dm[2], Dm[3], pre);

    // 4. per-world SSM
    for (int i = 0; i < 4; i++) {
        int ds = STATES[i];
        dim3 gSq(ds / 64, ds / 64);

        // expm(0.1*A) via order-8 Horner Taylor: P <- I; P <- I + (0.1/k) A P
        k_identity<<<(ds * ds + 255) / 256, 256>>>(Pb, ds);
        float* cur = Pb; float* oth = Qb;
        for (int k = 8; k >= 1; k--) {
            k_gemm<<<gSq, 256>>>(Am[i], cur, oth, ds, ds, ds,
                                 0.1f / (float)k, GF_ADDI, nullptr, 0, nullptr);
            float* tmp = cur; cur = oth; oth = tmp;
        }
        // Ad now in `cur` (8 swaps -> back in Pb)

        // u = xe @ B_i   [4096, ds]
        k_gemm<<<dim3(ds / 64, 64), 256>>>(xe, Bm[i], ub, 4096, ds, 256,
                                           1.0f, 0, nullptr, 0, nullptr);

        // Hillis-Steele scan with matrix powers (10 levels)
        float* scur = ub; float* snxt = vb;
        float* pw = cur; float* pwo = oth;
        for (int l = 0; l < 10; l++) {
            k_scanlevel<<<dim3(ds / 64, 64), 256>>>(scur, pw, snxt, ds, 1 << l);
            { float* tmp = scur; scur = snxt; snxt = tmp; }
            if (l < 9) {
                k_gemm<<<gSq, 256>>>(pw, pw, pwo, ds, ds, ds,
                                     1.0f, 0, nullptr, 0, nullptr);
                float* tmp = pw; pw = pwo; pwo = tmp;
            }
        }
        // h in scur (== ub after 10 swaps)

        // pre += w[b,i] * (h @ C_i)
        k_gemm<<<dim3(256 / 64, 64), 256>>>(scur, Cm[i], pre, 4096, 256, ds,
                                            0.0f, GF_ALPHA_ROW | GF_BETA1, wb, i, nullptr);
    }

    // 5. out = pre @ ow + ob   [4096, 32000]
    k_gemm<<<dim3(32000 / 64, 4096 / 64), 256>>>(pre, ow, out, 4096, 32000, 256,
                                                 1.0f, GF_BIAS, nullptr, 0, ob);
    (void)in_sizes; (void)n_in; (void)out_size;
}

// round 10
// speedup vs baseline: 1.4206x; 1.4115x over previous
#include <cuda_runtime.h>
#include <cuda_bf16.h>
#include <cstdint>

// ---------------------------------------------------------------------------
// MultiWorldSSM: emb-gather -> router -> 4x (expm + parallel scan + C proj)
//                -> output GEMM [4096,256]x[256,32000]
// Round 9: output GEMM moved to bf16 tensor cores (mma.sync.m16n8k16) with
// 3-pass error-compensated split (AH*BH + AH*BL + AL*BH), fp32 accumulate.
// Scan / expm remain fp32 SIMT (precision-critical: explosive modes).
// ---------------------------------------------------------------------------

#define GF_ADDI      1   // C += I (square matrices)
#define GF_ALPHA_ROW 2   // alpha = alphaRow[(row>>10)*4 + awIdx]
#define GF_BETA1     4   // C += existing C
#define GF_BIAS      8   // C += bias[col]

// -------- static scratch (no allocations allowed) --------
__device__ float g_xe  [4 * 1024 * 256];   // embedded tokens
__device__ float g_pre [4 * 1024 * 256];   // weighted-sum accumulator
__device__ float g_u   [4 * 1024 * 512];   // scan ping
__device__ float g_v   [4 * 1024 * 512];   // scan pong
__device__ float g_P   [512 * 512];        // expm / power buffer A
__device__ float g_Q   [512 * 512];        // expm / power buffer B
__device__ float g_mean[4 * 256];
__device__ float g_w   [4 * 4];

// ---------------------------------------------------------------------------
__global__ void k_embed(const int* __restrict__ x, const float* __restrict__ emb,
                        float* __restrict__ xe) {
    int r = blockIdx.x;          // 0..4095
    int d = threadIdx.x;         // 0..63 (float4 lanes)
    int tok = x[r];
    reinterpret_cast<float4*>(xe)[(size_t)r * 64 + d] =
        reinterpret_cast<const float4*>(emb)[(size_t)tok * 64 + d];
}

__global__ void k_mean(const float* __restrict__ xe, float* __restrict__ mean) {
    int b = blockIdx.x, d = threadIdx.x;  // 4 blocks x 256 threads
    const float* p = xe + (size_t)b * 1024 * 256 + d;
    float s = 0.f;
    for (int t = 0; t < 1024; t++) s += p[(size_t)t * 256];
    mean[b * 256 + d] = s * (1.0f / 1024.0f);
}

__global__ void k_router(const float* __restrict__ mean,
                         const float* __restrict__ rw1, const float* __restrict__ rb1,
                         const float* __restrict__ rw2, const float* __restrict__ rb2,
                         float* __restrict__ w) {
    __shared__ float hid[4][64];
    __shared__ float logit[4][4];
    int j = threadIdx.x;  // 64 threads
    for (int b = 0; b < 4; b++) {
        float s = rb1[j];
        for (int d = 0; d < 256; d++) s = fmaf(mean[b * 256 + d], rw1[d * 64 + j], s);
        hid[b][j] = fmaxf(s, 0.f);
    }
    __syncthreads();
    if (j < 16) {
        int b = j >> 2, i = j & 3;
        float s = rb2[i];
        for (int k = 0; k < 64; k++) s = fmaf(hid[b][k], rw2[k * 4 + i], s);
        logit[b][i] = s;
    }
    __syncthreads();
    if (j < 4) {
        int b = j;
        float mx = -1e30f;
        for (int i = 0; i < 4; i++) mx = fmaxf(mx, logit[b][i]);
        float e[4], se = 0.f;
        for (int i = 0; i < 4; i++) { e[i] = __expf(logit[b][i] - mx); se += e[i]; }
        for (int i = 0; i < 4; i++) w[b * 4 + i] = e[i] / se;
    }
}

// pre[r,d] = xe[r,d] * sum_i w[b,i] * D_i[d]   (initializes the accumulator)
__global__ void k_dterm(const float* __restrict__ xe, const float* __restrict__ w,
                        const float* __restrict__ D0, const float* __restrict__ D1,
                        const float* __restrict__ D2, const float* __restrict__ D3,
                        float* __restrict__ pre) {
    int r = blockIdx.x, d = threadIdx.x;
    int b = r >> 10;
    float wd = w[b * 4 + 0] * D0[d] + w[b * 4 + 1] * D1[d]
             + w[b * 4 + 2] * D2[d] + w[b * 4 + 3] * D3[d];
    size_t idx = (size_t)r * 256 + d;
    pre[idx] = xe[idx] * wd;
}

__global__ void k_identity(float* __restrict__ P, int n) {
    int i = blockIdx.x * blockDim.x + threadIdx.x;
    if (i < n * n) P[i] = (i / n == i % n) ? 1.0f : 0.0f;
}

// ---------------------------------------------------------------------------
// Generic fp32 GEMM: C = f(alpha * A[MxK] @ B[KxN]).  M,N mult of 64, K mult of 16.
// (used for expm, power squaring, u = xe@B, C-projection)
// ---------------------------------------------------------------------------
__global__ void k_gemm(const float* __restrict__ A, const float* __restrict__ B,
                       float* __restrict__ C, int M, int N, int K,
                       float alpha, int flags,
                       const float* __restrict__ alphaRow, int awIdx,
                       const float* __restrict__ bias) {
    __shared__ float As[16][65];
    __shared__ float Bs[16][64];
    int n0 = blockIdx.x * 64;
    int m0 = blockIdx.y * 64;
    int t = threadIdx.x;          // 256
    int tx = t & 15, ty = t >> 4;
    float acc[4][4] = {};
    for (int kt = 0; kt < K; kt += 16) {
        #pragma unroll
        for (int i = 0; i < 4; i++) {
            int e = t + i * 256;
            int m = e >> 4, k = e & 15;
            As[k][m] = A[(size_t)(m0 + m) * K + kt + k];
        }
        #pragma unroll
        for (int i = 0; i < 4; i++) {
            int e = t + i * 256;
            int k = e >> 6, n = e & 63;
            Bs[k][n] = B[(size_t)(kt + k) * N + n0 + n];
        }
        __syncthreads();
        #pragma unroll
        for (int k = 0; k < 16; k++) {
            float a[4], b[4];
            #pragma unroll
            for (int i = 0; i < 4; i++) a[i] = As[k][ty * 4 + i];
            #pragma unroll
            for (int j = 0; j < 4; j++) b[j] = Bs[k][tx * 4 + j];
            #pragma unroll
            for (int i = 0; i < 4; i++)
                #pragma unroll
                for (int j = 0; j < 4; j++)
                    acc[i][j] = fmaf(a[i], b[j], acc[i][j]);
        }
        __syncthreads();
    }
    #pragma unroll
    for (int i = 0; i < 4; i++) {
        int r = m0 + ty * 4 + i;
        float a = (flags & GF_ALPHA_ROW) ? alphaRow[(r >> 10) * 4 + awIdx] : alpha;
        #pragma unroll
        for (int j = 0; j < 4; j++) {
            int c = n0 + tx * 4 + j;
            float v = a * acc[i][j];
            if ((flags & GF_ADDI) && r == c) v += 1.0f;
            size_t idx = (size_t)r * N + c;
            if (flags & GF_BETA1) v += C[idx];
            if (flags & GF_BIAS) v += bias[c];
            C[idx] = v;
        }
    }
}

// ---------------------------------------------------------------------------
// One Hillis-Steele scan level: dst[t] = src[t] + (pos>=off ? src[t-off]@P : 0)
// ---------------------------------------------------------------------------
__global__ void k_scanlevel(const float* __restrict__ src, const float* __restrict__ P,
                            float* __restrict__ dst, int N, int off) {
    int n0 = blockIdx.x * 64;
    int m0 = blockIdx.y * 64;
    int p0 = m0 & 1023;
    int t = threadIdx.x;
    if (p0 + 63 < off) {   // whole block is pure copy
        #pragma unroll
        for (int i = 0; i < 16; i++) {
            int e = t + i * 256;
            int m = e >> 6, n = e & 63;
            size_t idx = (size_t)(m0 + m) * N + n0 + n;
            dst[idx] = src[idx];
        }
        return;
    }
    __shared__ float As[16][65];
    __shared__ float Bs[16][64];
    int tx = t & 15, ty = t >> 4;
    float acc[4][4] = {};
    for (int kt = 0; kt < N; kt += 16) {
        #pragma unroll
        for (int i = 0; i < 4; i++) {
            int e = t + i * 256;
            int m = e >> 4, k = e & 15;
            int rA = m0 + m - off; if (rA < 0) rA = 0;
            As[k][m] = src[(size_t)rA * N + kt + k];
        }
        #pragma unroll
        for (int i = 0; i < 4; i++) {
            int e = t + i * 256;
            int k = e >> 6, n = e & 63;
            Bs[k][n] = P[(size_t)(kt + k) * N + n0 + n];
        }
        __syncthreads();
        #pragma unroll
        for (int k = 0; k < 16; k++) {
            float a[4], b[4];
            #pragma unroll
            for (int i = 0; i < 4; i++) a[i] = As[k][ty * 4 + i];
            #pragma unroll
            for (int j = 0; j < 4; j++) b[j] = Bs[k][tx * 4 + j];
            #pragma unroll
            for (int i = 0; i < 4; i++)
                #pragma unroll
                for (int j = 0; j < 4; j++)
                    acc[i][j] = fmaf(a[i], b[j], acc[i][j]);
        }
        __syncthreads();
    }
    #pragma unroll
    for (int i = 0; i < 4; i++) {
        int r = m0 + ty * 4 + i;
        int pos = r & 1023;
        #pragma unroll
        for (int j = 0; j < 4; j++) {
            int c = n0 + tx * 4 + j;
            size_t idx = (size_t)r * N + c;
            float v = src[idx];
            if (pos >= off) v += acc[i][j];
            dst[idx] = v;
        }
    }
}

// ---------------------------------------------------------------------------
// Output GEMM on tensor cores: C[M,N] = A[M,K] @ B[K,N] + bias, via bf16
// 3-pass split (AH*BH + AH*BL + AL*BH), fp32 accumulate.
// Block tile 128x128, 8 warps (2M x 4N), warp tile 64x32. K mult of 16.
// ---------------------------------------------------------------------------
__device__ __forceinline__ void ldm_x4(uint32_t* r, uint32_t addr) {
    asm volatile("ldmatrix.sync.aligned.m8n8.x4.shared.b16 {%0,%1,%2,%3}, [%4];"
                 : "=r"(r[0]), "=r"(r[1]), "=r"(r[2]), "=r"(r[3]) : "r"(addr));
}
__device__ __forceinline__ void ldm_x2_t(uint32_t* r, uint32_t addr) {
    asm volatile("ldmatrix.sync.aligned.m8n8.x2.trans.shared.b16 {%0,%1}, [%2];"
                 : "=r"(r[0]), "=r"(r[1]) : "r"(addr));
}
__device__ __forceinline__ void mma_bf16(float* d, const uint32_t* a, const uint32_t* b) {
    asm volatile("mma.sync.aligned.m16n8k16.row.col.f32.bf16.bf16.f32 "
                 "{%0,%1,%2,%3}, {%4,%5,%6,%7}, {%8,%9}, {%0,%1,%2,%3};"
                 : "+f"(d[0]), "+f"(d[1]), "+f"(d[2]), "+f"(d[3])
                 : "r"(a[0]), "r"(a[1]), "r"(a[2]), "r"(a[3]),
                   "r"(b[0]), "r"(b[1]));
}

__global__ __launch_bounds__(256)
void k_gemm_out_tc(const float* __restrict__ A, const float* __restrict__ B,
                   float* __restrict__ C, int M, int N, int K,
                   const float* __restrict__ bias) {
    __shared__ __align__(16) __nv_bfloat16 sAH[128][24];   // row stride 48B
    __shared__ __align__(16) __nv_bfloat16 sAL[128][24];
    __shared__ __align__(16) __nv_bfloat16 sBH[16][136];   // row stride 272B
    __shared__ __align__(16) __nv_bfloat16 sBL[16][136];

    int t = threadIdx.x;
    int lane = t & 31, wid = t >> 5;
    int warpM = wid >> 2, warpN = wid & 3;   // 2 x 4 warps
    int m0 = blockIdx.y * 128;
    int n0 = blockIdx.x * 128;

    float acc[4][4][4] = {};   // [mtile][ntile][reg]

    for (int kt = 0; kt < K; kt += 16) {
        // ---- A tile: 128m x 16k fp32 -> split hi/lo bf16 ----
        #pragma unroll
        for (int i = 0; i < 2; i++) {
            int idx4 = t + i * 256;        // 512 float4 slots
            int m = idx4 >> 2, kq = idx4 & 3;
            float4 v = *reinterpret_cast<const float4*>(
                &A[(size_t)(m0 + m) * K + kt + kq * 4]);
            __nv_bfloat16 h0 = __float2bfloat16_rn(v.x);
            __nv_bfloat16 h1 = __float2bfloat16_rn(v.y);
            __nv_bfloat16 h2 = __float2bfloat16_rn(v.z);
            __nv_bfloat16 h3 = __float2bfloat16_rn(v.w);
            __nv_bfloat16 l0 = __float2bfloat16_rn(v.x - __bfloat162float(h0));
            __nv_bfloat16 l1 = __float2bfloat16_rn(v.y - __bfloat162float(h1));
            __nv_bfloat16 l2 = __float2bfloat16_rn(v.z - __bfloat162float(h2));
            __nv_bfloat16 l3 = __float2bfloat16_rn(v.w - __bfloat162float(h3));
            __nv_bfloat162* pH = reinterpret_cast<__nv_bfloat162*>(&sAH[m][kq * 4]);
            __nv_bfloat162* pL = reinterpret_cast<__nv_bfloat162*>(&sAL[m][kq * 4]);
            pH[0] = __nv_bfloat162(h0, h1); pH[1] = __nv_bfloat162(h2, h3);
            pL[0] = __nv_bfloat162(l0, l1); pL[1] = __nv_bfloat162(l2, l3);
        }
        // ---- B tile: 16k x 128n fp32 -> split hi/lo bf16 ----
        #pragma unroll
        for (int i = 0; i < 2; i++) {
            int idx4 = t + i * 256;
            int k = idx4 >> 5, nq = idx4 & 31;
            float4 v = *reinterpret_cast<const float4*>(
                &B[(size_t)(kt + k) * N + n0 + nq * 4]);
            __nv_bfloat16 h0 = __float2bfloat16_rn(v.x);
            __nv_bfloat16 h1 = __float2bfloat16_rn(v.y);
            __nv_bfloat16 h2 = __float2bfloat16_rn(v.z);
            __nv_bfloat16 h3 = __float2bfloat16_rn(v.w);
            __nv_bfloat16 l0 = __float2bfloat16_rn(v.x - __bfloat162float(h0));
            __nv_bfloat16 l1 = __float2bfloat16_rn(v.y - __bfloat162float(h1));
            __nv_bfloat16 l2 = __float2bfloat16_rn(v.z - __bfloat162float(h2));
            __nv_bfloat16 l3 = __float2bfloat16_rn(v.w - __bfloat162float(h3));
            __nv_bfloat162* pH = reinterpret_cast<__nv_bfloat162*>(&sBH[k][nq * 4]);
            __nv_bfloat162* pL = reinterpret_cast<__nv_bfloat162*>(&sBL[k][nq * 4]);
            pH[0] = __nv_bfloat162(h0, h1); pH[1] = __nv_bfloat162(h2, h3);
            pL[0] = __nv_bfloat162(l0, l1); pL[1] = __nv_bfloat162(l2, l3);
        }
        __syncthreads();

        // ---- fragments ----
        uint32_t aH[4][4], aL[4][4], bH[4][2], bL[4][2];
        int arow_off = ((lane >> 3) & 1) * 8 + (lane & 7);
        int ako = (lane >> 4) * 8;
        #pragma unroll
        for (int mt = 0; mt < 4; mt++) {
            int row = warpM * 64 + mt * 16 + arow_off;
            ldm_x4(aH[mt], (uint32_t)__cvta_generic_to_shared(&sAH[row][ako]));
            ldm_x4(aL[mt], (uint32_t)__cvta_generic_to_shared(&sAL[row][ako]));
        }
        int bkrow = lane & 15;
        #pragma unroll
        for (int nt = 0; nt < 4; nt++) {
            int ncol = warpN * 32 + nt * 8;
            ldm_x2_t(bH[nt], (uint32_t)__cvta_generic_to_shared(&sBH[bkrow][ncol]));
            ldm_x2_t(bL[nt], (uint32_t)__cvta_generic_to_shared(&sBL[bkrow][ncol]));
        }
        // ---- 3-pass split MMA ----
        #pragma unroll
        for (int mt = 0; mt < 4; mt++)
            #pragma unroll
            for (int nt = 0; nt < 4; nt++) {
                mma_bf16(acc[mt][nt], aH[mt], bH[nt]);
                mma_bf16(acc[mt][nt], aH[mt], bL[nt]);
                mma_bf16(acc[mt][nt], aL[mt], bH[nt]);
            }
        __syncthreads();
    }

    // ---- epilogue: + bias, store fp32 ----
    int g = lane >> 2, tg = lane & 3;
    #pragma unroll
    for (int nt = 0; nt < 4; nt++) {
        int c = n0 + warpN * 32 + nt * 8 + tg * 2;
        float b0 = bias[c], b1 = bias[c + 1];
        #pragma unroll
        for (int mt = 0; mt < 4; mt++) {
            int r = m0 + warpM * 64 + mt * 16 + g;
            float2 v0 = make_float2(acc[mt][nt][0] + b0, acc[mt][nt][1] + b1);
            float2 v1 = make_float2(acc[mt][nt][2] + b0, acc[mt][nt][3] + b1);
            *reinterpret_cast<float2*>(&C[(size_t)r * N + c]) = v0;
            *reinterpret_cast<float2*>(&C[(size_t)(r + 8) * N + c]) = v1;
        }
    }
}

// ---------------------------------------------------------------------------
extern "C" void kernel_launch(void* const* d_in, const int* in_sizes, int n_in,
                              void* d_out, int out_size) {
    const int*   x    = (const int*)  d_in[0];
    const float* emb  = (const float*)d_in[1];
    const float* Am[4] = {(const float*)d_in[2],  (const float*)d_in[6],
                          (const float*)d_in[10], (const float*)d_in[14]};
    const float* Bm[4] = {(const float*)d_in[3],  (const float*)d_in[7],
                          (const float*)d_in[11], (const float*)d_in[15]};
    const float* Cm[4] = {(const float*)d_in[4],  (const float*)d_in[8],
                          (const float*)d_in[12], (const float*)d_in[16]};
    const float* Dm[4] = {(const float*)d_in[5],  (const float*)d_in[9],
                          (const float*)d_in[13], (const float*)d_in[17]};
    const float* rw1 = (const float*)d_in[18];
    const float* rb1 = (const float*)d_in[19];
    const float* rw2 = (const float*)d_in[20];
    const float* rb2 = (const float*)d_in[21];
    const float* ow  = (const float*)d_in[22];
    const float* ob  = (const float*)d_in[23];
    float* out = (float*)d_out;

    float *xe, *pre, *ub, *vb, *Pb, *Qb, *meanb, *wb;
    cudaGetSymbolAddress((void**)&xe,    g_xe);
    cudaGetSymbolAddress((void**)&pre,   g_pre);
    cudaGetSymbolAddress((void**)&ub,    g_u);
    cudaGetSymbolAddress((void**)&vb,    g_v);
    cudaGetSymbolAddress((void**)&Pb,    g_P);
    cudaGetSymbolAddress((void**)&Qb,    g_Q);
    cudaGetSymbolAddress((void**)&meanb, g_mean);
    cudaGetSymbolAddress((void**)&wb,    g_w);

    const int STATES[4] = {64, 128, 256, 512};

    // 1. embedding gather
    k_embed<<<4096, 64>>>(x, emb, xe);
    // 2. router
    k_mean<<<4, 256>>>(xe, meanb);
    k_router<<<1, 64>>>(meanb, rw1, rb1, rw2, rb2, wb);
    // 3. init accumulator with the (sum_i w_i * D_i) * xe term
    k_dterm<<<4096, 256>>>(xe, wb, Dm[0], Dm[1], Dm[2], Dm[3], pre);

    // 4. per-world SSM
    for (int i = 0; i < 4; i++) {
        int ds = STATES[i];
        dim3 gSq(ds / 64, ds / 64);

        // expm(0.1*A) via order-8 Horner Taylor: P <- I; P <- I + (0.1/k) A P
        k_identity<<<(ds * ds + 255) / 256, 256>>>(Pb, ds);
        float* cur = Pb; float* oth = Qb;
        for (int k = 8; k >= 1; k--) {
            k_gemm<<<gSq, 256>>>(Am[i], cur, oth, ds, ds, ds,
                                 0.1f / (float)k, GF_ADDI, nullptr, 0, nullptr);
            float* tmp = cur; cur = oth; oth = tmp;
        }
        // Ad now in `cur`

        // u = xe @ B_i   [4096, ds]
        k_gemm<<<dim3(ds / 64, 64), 256>>>(xe, Bm[i], ub, 4096, ds, 256,
                                           1.0f, 0, nullptr, 0, nullptr);

        // Hillis-Steele scan with matrix powers (10 levels)
        float* scur = ub; float* snxt = vb;
        float* pw = cur; float* pwo = oth;
        for (int l = 0; l < 10; l++) {
            k_scanlevel<<<dim3(ds / 64, 64), 256>>>(scur, pw, snxt, ds, 1 << l);
            { float* tmp = scur; scur = snxt; snxt = tmp; }
            if (l < 9) {
                k_gemm<<<gSq, 256>>>(pw, pw, pwo, ds, ds, ds,
                                     1.0f, 0, nullptr, 0, nullptr);
                float* tmp = pw; pw = pwo; pwo = tmp;
            }
        }

        // pre += w[b,i] * (h @ C_i)
        k_gemm<<<dim3(256 / 64, 64), 256>>>(scur, Cm[i], pre, 4096, 256, ds,
                                            0.0f, GF_ALPHA_ROW | GF_BETA1, wb, i, nullptr);
    }

    // 5. out = pre @ ow + ob   [4096, 32000]  — tensor cores, bf16 split x3
    k_gemm_out_tc<<<dim3(32000 / 128, 4096 / 128), 256>>>(pre, ow, out,
                                                          4096, 32000, 256, ob);
    (void)in_sizes; (void)n_in; (void)out_size;
}